// round 13
// baseline (speedup 1.0000x reference)
#include <cuda_runtime.h>
#include <cstdint>

// ---------------------------------------------------------------------------
// BinarizedLinear: out = BN( sign(x) @ sign(W)^T )   (bias cancels under BN)
// compute_103 PTX => no tcgen05. Dual-pipe GEMM, R13 (= R11 + 40/88 split):
//   8 tensor warps: mma.sync m16n8k32 s8, warp tile 16M x 40N (cols 0..39)
//                   (5th B frag: ldsm_x4 at rows 32..47, use r0/r2 only)
//   8 popc warps:   XOR + CSA popcount (POPC quarter-rate), cols 40..127
//   3-stage cp.async pipeline, one barrier per k-chunk, 2 CTAs/SM.
// ---------------------------------------------------------------------------

#define B_DIM   8192
#define K_DIM   4096
#define O_DIM   4096

__device__ __align__(16) int8_t   g_bx8[(size_t)B_DIM * K_DIM];
__device__ __align__(16) int8_t   g_bw8[(size_t)O_DIM * K_DIM];
__device__ __align__(16) uint16_t g_bxbit[(size_t)B_DIM * K_DIM / 16];
__device__ __align__(16) uint16_t g_bwbit[(size_t)O_DIM * K_DIM / 16];
__device__ __align__(16) float g_sum[O_DIM];
__device__ __align__(16) float g_ss[O_DIM];
__device__ __align__(16) float g_scale[O_DIM];
__device__ __align__(16) float g_shift[O_DIM];

// ------------------------------- helpers ------------------------------------
__device__ __forceinline__ uint32_t smem_u32(const void* p) {
    uint32_t a;
    asm("{ .reg .u64 t; cvta.to.shared.u64 t, %1; cvt.u32.u64 %0, t; }" : "=r"(a) : "l"(p));
    return a;
}
__device__ __forceinline__ void cp_async16(uint32_t s, const void* g) {
    asm volatile("cp.async.cg.shared.global [%0], [%1], 16;" :: "r"(s), "l"(g));
}
#define CP_COMMIT() asm volatile("cp.async.commit_group;")

__device__ __forceinline__ void ldsm_x4(uint32_t& r0, uint32_t& r1, uint32_t& r2, uint32_t& r3,
                                        uint32_t addr) {
    asm volatile("ldmatrix.sync.aligned.m8n8.x4.shared.b16 {%0,%1,%2,%3}, [%4];"
                 : "=r"(r0), "=r"(r1), "=r"(r2), "=r"(r3) : "r"(addr));
}
__device__ __forceinline__ void mma_s8(int& c0, int& c1, int& c2, int& c3,
                                       uint32_t a0, uint32_t a1, uint32_t a2, uint32_t a3,
                                       uint32_t b0, uint32_t b1) {
    asm volatile("mma.sync.aligned.m16n8k32.row.col.s32.s8.s8.s32 "
                 "{%0,%1,%2,%3}, {%4,%5,%6,%7}, {%8,%9}, {%0,%1,%2,%3};"
                 : "+r"(c0), "+r"(c1), "+r"(c2), "+r"(c3)
                 : "r"(a0), "r"(a1), "r"(a2), "r"(a3), "r"(b0), "r"(b1));
}
// Popcount of the 128-bit XOR via carry-save tree: 3 POPC instead of 4.
__device__ __forceinline__ uint32_t popc_csa4(uint4 a, uint4 b) {
    uint32_t x0 = a.x ^ b.x, x1 = a.y ^ b.y, x2 = a.z ^ b.z, x3 = a.w ^ b.w;
    uint32_t t  = x0 ^ x1;
    uint32_t s1 = t ^ x2;
    uint32_t c1 = (x0 & x1) | (x2 & t);
    uint32_t s2 = s1 ^ x3;
    uint32_t c2 = s1 & x3;
    return __popc(s2) + 2u * (__popc(c1) + __popc(c2));
}

// ------------------------------- binarize -----------------------------------
__device__ __forceinline__ uint32_t pack4(float4 v) {
    uint32_t w = 0;
    float f[4] = {v.x, v.y, v.z, v.w};
#pragma unroll
    for (int j = 0; j < 4; j++) {
        int s = (f[j] > 0.0f) ? 1 : ((f[j] < 0.0f) ? -1 : 0);
        w |= (uint32_t)(uint8_t)(int8_t)s << (8 * j);
    }
    return w;
}
__device__ __forceinline__ uint32_t sgn4(float4 v) {
    return (__float_as_uint(v.x) >> 31) | ((__float_as_uint(v.y) >> 31) << 1)
         | ((__float_as_uint(v.z) >> 31) << 2) | ((__float_as_uint(v.w) >> 31) << 3);
}
__global__ void binarize_all(const float* __restrict__ x, const float* __restrict__ w,
                             int nx16, int ntot16) {
    int i = blockIdx.x * blockDim.x + threadIdx.x;
    if (i >= ntot16) return;
    const float* src;
    int8_t* dst;
    uint16_t* dbit;
    int j;
    if (i < nx16) { src = x; dst = g_bx8; dbit = g_bxbit; j = i; }
    else          { src = w; dst = g_bw8; dbit = g_bwbit; j = i - nx16; }
    const float4* p = reinterpret_cast<const float4*>(src) + (size_t)j * 4;
    float4 v0 = p[0], v1 = p[1], v2 = p[2], v3 = p[3];
    uint4 o;
    o.x = pack4(v0); o.y = pack4(v1); o.z = pack4(v2); o.w = pack4(v3);
    reinterpret_cast<uint4*>(dst)[j] = o;
    dbit[j] = (uint16_t)(sgn4(v0) | (sgn4(v1) << 4) | (sgn4(v2) << 8) | (sgn4(v3) << 12));
}

// --------------------------------- GEMM -------------------------------------
// CTA 128(M) x 128(N). KC = 128 elements. 3 SMEM stages, one barrier per kc.
// Stage: A s8 (128x128 sw) | B s8 rows0..47 (sw) | A bits (128x16B) | B bits (88x16B)
static constexpr int KC = 128;
static constexpr int NKC = K_DIM / KC;              // 32
static constexpr int OFF_A    = 0;                  // 16384 B
static constexpr int OFF_B    = 16384;              // 6144 B (48 rows, 40 used + pad)
static constexpr int OFF_ABIT = 22528;              // 2048 B
static constexpr int OFF_BBIT = 24576;              // 1408 B (88 rows x 16B)
static constexpr int STAGE_B  = 25984;
static constexpr int SMEM_BYTES = 3 * STAGE_B;      // 77952
static constexpr int NTHREADS = 512;
static constexpr int KB8 = K_DIM / 8;               // bit-row stride in bytes

__device__ __forceinline__ uint32_t swz(int row, int cb) {  // cb: 16B chunk 0..7
    return (uint32_t)(row * 128 + ((cb ^ (row & 7)) << 4));
}

__device__ __forceinline__ void load_buf(uint32_t sbase, int m0, int n0, int kc, int tid) {
    const int8_t* ga = g_bx8 + (size_t)m0 * K_DIM + kc * KC;
    const int8_t* gb = g_bw8 + (size_t)n0 * K_DIM + kc * KC;
#pragma unroll
    for (int i = 0; i < 2; i++) {                    // A s8: 1024 chunks
        int c = tid + i * NTHREADS;
        int row = c >> 3, cb = c & 7;
        cp_async16(sbase + OFF_A + swz(row, cb), ga + (size_t)row * K_DIM + cb * 16);
    }
    if (tid < 384) {                                 // B s8 rows 0..47 (48 rows)
        int row = tid >> 3, cb = tid & 7;
        cp_async16(sbase + OFF_B + swz(row, cb), gb + (size_t)row * K_DIM + cb * 16);
    } else {                                         // A bits: 128 rows x 16B
        int r = tid - 384;
        const char* gx = (const char*)g_bxbit + (size_t)(m0 + r) * KB8 + kc * 16;
        cp_async16(sbase + OFF_ABIT + r * 16, gx);
    }
    if (tid < 88) {                                  // B bits: W rows n0+40..n0+127
        const char* gw = (const char*)g_bwbit + (size_t)(n0 + 40 + tid) * KB8 + kc * 16;
        cp_async16(sbase + OFF_BBIT + tid * 16, gw);
    }
}

__global__ void __launch_bounds__(NTHREADS, 2) gemm_kernel(float* __restrict__ out) {
    extern __shared__ char smem[];
    uint32_t sb = smem_u32(smem);

    const int tid = threadIdx.x, lane = tid & 31, wid = tid >> 5;
    const int m0 = blockIdx.y * 128, n0 = blockIdx.x * 128;

    const bool is_tc = (wid < 8);
    const int wm = (wid & 7) * 16;       // row base for both roles
    const int lrow = lane & 15;
    const int lk16 = (lane >> 4) & 1;
    const int gm = lane >> 3;            // 0..3
    const int gn = lane & 7;             // 0..7

    // tensor: acc[0..19] s32 (5 nt groups). popc: acc[0..23] = 4 rows x (5 packed + 1 u32)
    uint32_t acc[24];
#pragma unroll
    for (int i = 0; i < 24; i++) acc[i] = 0;

    load_buf(sb, m0, n0, 0, tid);
    CP_COMMIT();
    load_buf(sb + STAGE_B, m0, n0, 1, tid);
    CP_COMMIT();

    int st = 0;
    for (int kc = 0; kc < NKC; kc++) {
        if (kc < NKC - 1) asm volatile("cp.async.wait_group 1;");
        else              asm volatile("cp.async.wait_group 0;");
        __syncthreads();

        if (kc + 2 < NKC) {
            int st2 = st + 2; if (st2 >= 3) st2 -= 3;
            load_buf(sb + (uint32_t)st2 * STAGE_B, m0, n0, kc + 2, tid);
            CP_COMMIT();
        }

        const uint32_t cur = (uint32_t)st * STAGE_B;
        if (is_tc) {
            const uint32_t Ab = sb + cur + OFF_A, Bb = sb + cur + OFF_B;
#pragma unroll
            for (int ks = 0; ks < 4; ks++) {
                const int cb = ks * 2 + lk16;
                uint32_t a[4], b[2][4], b2[4];
                ldsm_x4(a[0], a[1], a[2], a[3], Ab + swz(wm + lrow, cb));
#pragma unroll
                for (int bt = 0; bt < 2; bt++)
                    ldsm_x4(b[bt][0], b[bt][1], b[bt][2], b[bt][3],
                            Bb + swz(bt * 16 + lrow, cb));
                // rows 32..47; only rows 32..39 (r0 k-lo, r2 k-hi) are used
                ldsm_x4(b2[0], b2[1], b2[2], b2[3], Bb + swz(32 + lrow, cb));
#pragma unroll
                for (int nt = 0; nt < 4; nt++) {
                    const int ix = nt * 4;
                    uint32_t blo = b[nt >> 1][nt & 1];
                    uint32_t bhi = b[nt >> 1][(nt & 1) + 2];
                    mma_s8((int&)acc[ix], (int&)acc[ix + 1], (int&)acc[ix + 2], (int&)acc[ix + 3],
                           a[0], a[1], a[2], a[3], blo, bhi);
                }
                mma_s8((int&)acc[16], (int&)acc[17], (int&)acc[18], (int&)acc[19],
                       a[0], a[1], a[2], a[3], b2[0], b2[2]);
            }
        } else {
            const char* Abit = smem + cur + OFF_ABIT;
            const char* Bbit = smem + cur + OFF_BBIT;
            uint4 Av[4];
#pragma unroll
            for (int r = 0; r < 4; r++)
                Av[r] = *reinterpret_cast<const uint4*>(Abit + (wm + gm * 4 + r) * 16);
#pragma unroll
            for (int cp = 0; cp < 5; cp++) {
                uint4 B0 = *reinterpret_cast<const uint4*>(Bbit + ((2 * cp) * 8 + gn) * 16);
                uint4 B1 = *reinterpret_cast<const uint4*>(Bbit + ((2 * cp + 1) * 8 + gn) * 16);
#pragma unroll
                for (int r = 0; r < 4; r++) {
                    uint32_t s0 = popc_csa4(Av[r], B0);
                    uint32_t s1 = popc_csa4(Av[r], B1);
                    acc[r * 6 + cp] += s0 + (s1 << 16);   // u16x2, max 4096/lane
                }
            }
            {   // single col group: cols 120..127 (Bbit rows 80..87)
                uint4 Bv = *reinterpret_cast<const uint4*>(Bbit + (80 + gn) * 16);
#pragma unroll
                for (int r = 0; r < 4; r++)
                    acc[r * 6 + 5] += popc_csa4(Av[r], Bv);
            }
        }
        if (++st == 3) st = 0;
    }

    // ----------------------------- epilogue ---------------------------------
    if (is_tc) {
        const int gq = lane >> 2, tg = lane & 3;
#pragma unroll
        for (int nt = 0; nt < 5; nt++) {
            const int ix = nt * 4;
            int col = n0 + nt * 8 + 2 * tg;
            int row0 = m0 + wm + gq;
            float2 v0 = make_float2((float)(int)acc[ix], (float)(int)acc[ix + 1]);
            float2 v1 = make_float2((float)(int)acc[ix + 2], (float)(int)acc[ix + 3]);
            *reinterpret_cast<float2*>(out + (size_t)row0 * O_DIM + col) = v0;
            *reinterpret_cast<float2*>(out + (size_t)(row0 + 8) * O_DIM + col) = v1;
        }
    } else {
#pragma unroll
        for (int r = 0; r < 4; r++) {
            const int row = m0 + wm + gm * 4 + r;
            float* orow = out + (size_t)row * O_DIM + n0 + 40;
#pragma unroll
            for (int cp = 0; cp < 5; cp++) {
                uint32_t a = acc[r * 6 + cp];
                int lo = (int)(a & 0xFFFFu), hi = (int)(a >> 16);
                orow[(2 * cp) * 8 + gn]     = (float)(K_DIM - 2 * lo);
                orow[(2 * cp + 1) * 8 + gn] = (float)(K_DIM - 2 * hi);
            }
            orow[80 + gn] = (float)(K_DIM - 2 * (int)acc[r * 6 + 5]);
        }
    }
}

// ------------------------------ BatchNorm -----------------------------------
__global__ void bn_zero() {
    int i = blockIdx.x * blockDim.x + threadIdx.x;
    if (i < O_DIM) { g_sum[i] = 0.f; g_ss[i] = 0.f; }
}
__global__ void bn_reduce(const float* __restrict__ d) {
    int col = blockIdx.x * 256 + threadIdx.x;
    const float* p = d + (size_t)blockIdx.y * 256 * O_DIM + col;
    float s = 0.f, ss = 0.f;
#pragma unroll 8
    for (int r = 0; r < 256; r++) {
        float v = p[(size_t)r * O_DIM];
        s += v;
        ss = fmaf(v, v, ss);
    }
    atomicAdd(&g_sum[col], s);
    atomicAdd(&g_ss[col], ss);
}
__global__ void bn_params() {
    int c = blockIdx.x * blockDim.x + threadIdx.x;
    if (c < O_DIM) {
        float mean = g_sum[c] * (1.0f / B_DIM);
        float var = g_ss[c] * (1.0f / B_DIM) - mean * mean;
        float sc = rsqrtf(var + 1e-5f);
        g_scale[c] = sc;
        g_shift[c] = -mean * sc;
    }
}
__global__ void bn_apply(float* __restrict__ d) {
    int i = blockIdx.x * blockDim.x + threadIdx.x;
    float4 v = reinterpret_cast<float4*>(d)[i];
    int c = (i & (O_DIM / 4 - 1)) << 2;
    float4 sc = *reinterpret_cast<const float4*>(g_scale + c);
    float4 sh = *reinterpret_cast<const float4*>(g_shift + c);
    v.x = fmaf(v.x, sc.x, sh.x);
    v.y = fmaf(v.y, sc.y, sh.y);
    v.z = fmaf(v.z, sc.z, sh.z);
    v.w = fmaf(v.w, sc.w, sh.w);
    reinterpret_cast<float4*>(d)[i] = v;
}

// -------------------------------- launch -------------------------------------
extern "C" void kernel_launch(void* const* d_in, const int* in_sizes, int n_in,
                              void* d_out, int out_size) {
    const float* x = (const float*)d_in[0];
    const float* w = (const float*)d_in[1];
    float* out = (float*)d_out;

    cudaFuncSetAttribute(gemm_kernel, cudaFuncAttributeMaxDynamicSharedMemorySize, SMEM_BYTES);

    const int nx16 = B_DIM * K_DIM / 16;
    const int nt16 = nx16 + O_DIM * K_DIM / 16;
    binarize_all<<<(nt16 + 255) / 256, 256>>>(x, w, nx16, nt16);
    bn_zero<<<16, 256>>>();

    gemm_kernel<<<dim3(O_DIM / 128, B_DIM / 128), NTHREADS, SMEM_BYTES>>>(out);

    bn_reduce<<<dim3(O_DIM / 256, B_DIM / 256), 256>>>(out);
    bn_params<<<16, 256>>>();
    bn_apply<<<(B_DIM * O_DIM / 4) / 256, 256>>>(out);
}

// round 14
// speedup vs baseline: 1.1157x; 1.1157x over previous
#include <cuda_runtime.h>
#include <cstdint>

// ---------------------------------------------------------------------------
// BinarizedLinear: out = BN( sign(x) @ sign(W)^T )   (bias cancels under BN)
// compute_103 PTX => no tcgen05. Dual-pipe GEMM, R14 (= R11 + light BN fusion):
//   8 tensor warps: mma.sync m16n8k32 s8, warp tile 16M x 32N (cols 0..31)
//   8 popc warps:   XOR + CSA popcount (POPC quarter-rate), cols 32..127
//   3-stage cp.async pipeline, one barrier per k-chunk, 2 CTAs/SM.
//   BN column sums fused into epilogue with SERIALIZED (register-light)
//   reductions; bn_reduce pass removed.
// ---------------------------------------------------------------------------

#define B_DIM   8192
#define K_DIM   4096
#define O_DIM   4096

__device__ __align__(16) int8_t   g_bx8[(size_t)B_DIM * K_DIM];
__device__ __align__(16) int8_t   g_bw8[(size_t)O_DIM * K_DIM];
__device__ __align__(16) uint16_t g_bxbit[(size_t)B_DIM * K_DIM / 16];
__device__ __align__(16) uint16_t g_bwbit[(size_t)O_DIM * K_DIM / 16];
__device__ __align__(16) float g_sum[O_DIM];
__device__ __align__(16) float g_ss[O_DIM];
__device__ __align__(16) float g_scale[O_DIM];
__device__ __align__(16) float g_shift[O_DIM];

// ------------------------------- helpers ------------------------------------
__device__ __forceinline__ uint32_t smem_u32(const void* p) {
    uint32_t a;
    asm("{ .reg .u64 t; cvta.to.shared.u64 t, %1; cvt.u32.u64 %0, t; }" : "=r"(a) : "l"(p));
    return a;
}
__device__ __forceinline__ void cp_async16(uint32_t s, const void* g) {
    asm volatile("cp.async.cg.shared.global [%0], [%1], 16;" :: "r"(s), "l"(g));
}
#define CP_COMMIT() asm volatile("cp.async.commit_group;")

__device__ __forceinline__ void ldsm_x4(uint32_t& r0, uint32_t& r1, uint32_t& r2, uint32_t& r3,
                                        uint32_t addr) {
    asm volatile("ldmatrix.sync.aligned.m8n8.x4.shared.b16 {%0,%1,%2,%3}, [%4];"
                 : "=r"(r0), "=r"(r1), "=r"(r2), "=r"(r3) : "r"(addr));
}
__device__ __forceinline__ void mma_s8(int& c0, int& c1, int& c2, int& c3,
                                       uint32_t a0, uint32_t a1, uint32_t a2, uint32_t a3,
                                       uint32_t b0, uint32_t b1) {
    asm volatile("mma.sync.aligned.m16n8k32.row.col.s32.s8.s8.s32 "
                 "{%0,%1,%2,%3}, {%4,%5,%6,%7}, {%8,%9}, {%0,%1,%2,%3};"
                 : "+r"(c0), "+r"(c1), "+r"(c2), "+r"(c3)
                 : "r"(a0), "r"(a1), "r"(a2), "r"(a3), "r"(b0), "r"(b1));
}
// Popcount of the 128-bit XOR via carry-save tree: 3 POPC instead of 4.
__device__ __forceinline__ uint32_t popc_csa4(uint4 a, uint4 b) {
    uint32_t x0 = a.x ^ b.x, x1 = a.y ^ b.y, x2 = a.z ^ b.z, x3 = a.w ^ b.w;
    uint32_t t  = x0 ^ x1;
    uint32_t s1 = t ^ x2;
    uint32_t c1 = (x0 & x1) | (x2 & t);
    uint32_t s2 = s1 ^ x3;
    uint32_t c2 = s1 & x3;
    return __popc(s2) + 2u * (__popc(c1) + __popc(c2));
}

// ------------------------------- binarize -----------------------------------
__device__ __forceinline__ uint32_t pack4(float4 v) {
    uint32_t w = 0;
    float f[4] = {v.x, v.y, v.z, v.w};
#pragma unroll
    for (int j = 0; j < 4; j++) {
        int s = (f[j] > 0.0f) ? 1 : ((f[j] < 0.0f) ? -1 : 0);
        w |= (uint32_t)(uint8_t)(int8_t)s << (8 * j);
    }
    return w;
}
__device__ __forceinline__ uint32_t sgn4(float4 v) {
    return (__float_as_uint(v.x) >> 31) | ((__float_as_uint(v.y) >> 31) << 1)
         | ((__float_as_uint(v.z) >> 31) << 2) | ((__float_as_uint(v.w) >> 31) << 3);
}
__global__ void binarize_all(const float* __restrict__ x, const float* __restrict__ w,
                             int nx16, int ntot16) {
    int i = blockIdx.x * blockDim.x + threadIdx.x;
    if (i >= ntot16) return;
    const float* src;
    int8_t* dst;
    uint16_t* dbit;
    int j;
    if (i < nx16) { src = x; dst = g_bx8; dbit = g_bxbit; j = i; }
    else          { src = w; dst = g_bw8; dbit = g_bwbit; j = i - nx16; }
    const float4* p = reinterpret_cast<const float4*>(src) + (size_t)j * 4;
    float4 v0 = p[0], v1 = p[1], v2 = p[2], v3 = p[3];
    uint4 o;
    o.x = pack4(v0); o.y = pack4(v1); o.z = pack4(v2); o.w = pack4(v3);
    reinterpret_cast<uint4*>(dst)[j] = o;
    dbit[j] = (uint16_t)(sgn4(v0) | (sgn4(v1) << 4) | (sgn4(v2) << 8) | (sgn4(v3) << 12));
}

// --------------------------------- GEMM -------------------------------------
// CTA 128(M) x 128(N). KC = 128 elements. 3 SMEM stages, one barrier per kc.
// Stage: A s8 (128x128 sw) | B s8 rows0..31 (sw) | A bits (128x16B) | B bits (96x16B)
static constexpr int KC = 128;
static constexpr int NKC = K_DIM / KC;              // 32
static constexpr int OFF_A    = 0;                  // 16384 B
static constexpr int OFF_B    = 16384;              // 4096 B (32 rows)
static constexpr int OFF_ABIT = 20480;              // 2048 B
static constexpr int OFF_BBIT = 22528;              // 1536 B (96 rows x 16B)
static constexpr int STAGE_B  = 24064;
static constexpr int SMEM_BYTES = 3 * STAGE_B;      // 72192
static constexpr int NTHREADS = 512;
static constexpr int KB8 = K_DIM / 8;               // bit-row stride in bytes

__device__ __forceinline__ uint32_t swz(int row, int cb) {  // cb: 16B chunk 0..7
    return (uint32_t)(row * 128 + ((cb ^ (row & 7)) << 4));
}

__device__ __forceinline__ void load_buf(uint32_t sbase, int m0, int n0, int kc, int tid) {
    const int8_t* ga = g_bx8 + (size_t)m0 * K_DIM + kc * KC;
    const int8_t* gb = g_bw8 + (size_t)n0 * K_DIM + kc * KC;
#pragma unroll
    for (int i = 0; i < 2; i++) {                    // A s8: 1024 chunks
        int c = tid + i * NTHREADS;
        int row = c >> 3, cb = c & 7;
        cp_async16(sbase + OFF_A + swz(row, cb), ga + (size_t)row * K_DIM + cb * 16);
    }
    if (tid < 256) {                                 // B s8 rows 0..31: 256 chunks
        int row = tid >> 3, cb = tid & 7;
        cp_async16(sbase + OFF_B + swz(row, cb), gb + (size_t)row * K_DIM + cb * 16);
    } else if (tid < 384) {                          // A bits: 128 rows x 16B
        int r = tid - 256;
        const char* gx = (const char*)g_bxbit + (size_t)(m0 + r) * KB8 + kc * 16;
        cp_async16(sbase + OFF_ABIT + r * 16, gx);
    } else if (tid < 480) {                          // B bits: W rows n0+32..n0+127
        int r = tid - 384;
        const char* gw = (const char*)g_bwbit + (size_t)(n0 + 32 + r) * KB8 + kc * 16;
        cp_async16(sbase + OFF_BBIT + r * 16, gw);
    }
}

__global__ void __launch_bounds__(NTHREADS, 2) gemm_kernel(float* __restrict__ out) {
    extern __shared__ char smem[];
    uint32_t sb = smem_u32(smem);

    const int tid = threadIdx.x, lane = tid & 31, wid = tid >> 5;
    const int m0 = blockIdx.y * 128, n0 = blockIdx.x * 128;

    const bool is_tc = (wid < 8);
    const int wm = (wid & 7) * 16;       // row base for both roles
    const int lrow = lane & 15;
    const int lk16 = (lane >> 4) & 1;
    const int gm = lane >> 3;            // 0..3
    const int gn = lane & 7;             // 0..7

    uint32_t acc[24];                    // tensor uses 16 (s32); popc uses 24 packed
#pragma unroll
    for (int i = 0; i < 24; i++) acc[i] = 0;

    load_buf(sb, m0, n0, 0, tid);
    CP_COMMIT();
    load_buf(sb + STAGE_B, m0, n0, 1, tid);
    CP_COMMIT();

    int st = 0;
    for (int kc = 0; kc < NKC; kc++) {
        if (kc < NKC - 1) asm volatile("cp.async.wait_group 1;");
        else              asm volatile("cp.async.wait_group 0;");
        __syncthreads();

        if (kc + 2 < NKC) {
            int st2 = st + 2; if (st2 >= 3) st2 -= 3;
            load_buf(sb + (uint32_t)st2 * STAGE_B, m0, n0, kc + 2, tid);
            CP_COMMIT();
        }

        const uint32_t cur = (uint32_t)st * STAGE_B;
        if (is_tc) {
            const uint32_t Ab = sb + cur + OFF_A, Bb = sb + cur + OFF_B;
#pragma unroll
            for (int ks = 0; ks < 4; ks++) {
                const int cb = ks * 2 + lk16;
                uint32_t a[4], b[2][4];
                ldsm_x4(a[0], a[1], a[2], a[3], Ab + swz(wm + lrow, cb));
#pragma unroll
                for (int bt = 0; bt < 2; bt++)
                    ldsm_x4(b[bt][0], b[bt][1], b[bt][2], b[bt][3],
                            Bb + swz(bt * 16 + lrow, cb));
#pragma unroll
                for (int nt = 0; nt < 4; nt++) {
                    const int ix = nt * 4;
                    uint32_t blo = b[nt >> 1][nt & 1];
                    uint32_t bhi = b[nt >> 1][(nt & 1) + 2];
                    mma_s8((int&)acc[ix], (int&)acc[ix + 1], (int&)acc[ix + 2], (int&)acc[ix + 3],
                           a[0], a[1], a[2], a[3], blo, bhi);
                }
            }
        } else {
            const char* Abit = smem + cur + OFF_ABIT;
            const char* Bbit = smem + cur + OFF_BBIT;
            uint4 Av[4];
#pragma unroll
            for (int r = 0; r < 4; r++)
                Av[r] = *reinterpret_cast<const uint4*>(Abit + (wm + gm * 4 + r) * 16);
#pragma unroll
            for (int cp = 0; cp < 6; cp++) {
                uint4 B0 = *reinterpret_cast<const uint4*>(Bbit + ((2 * cp) * 8 + gn) * 16);
                uint4 B1 = *reinterpret_cast<const uint4*>(Bbit + ((2 * cp + 1) * 8 + gn) * 16);
#pragma unroll
                for (int r = 0; r < 4; r++) {
                    uint32_t s0 = popc_csa4(Av[r], B0);
                    uint32_t s1 = popc_csa4(Av[r], B1);
                    acc[r * 6 + cp] += s0 + (s1 << 16);   // u16x2, max 4096/lane
                }
            }
        }
        if (++st == 3) st = 0;
    }

    // ------------- epilogue: store + fused BN sums (register-light) ----------
    if (is_tc) {
        const int gq = lane >> 2, tg = lane & 3;
#pragma unroll
        for (int nt = 0; nt < 4; nt++) {
            const int ix = nt * 4;
            int col = n0 + nt * 8 + 2 * tg;
            int row0 = m0 + wm + gq;
            float f0 = (float)(int)acc[ix],     f1 = (float)(int)acc[ix + 1];
            float f2 = (float)(int)acc[ix + 2], f3 = (float)(int)acc[ix + 3];
            *reinterpret_cast<float2*>(out + (size_t)row0 * O_DIM + col) = make_float2(f0, f1);
            *reinterpret_cast<float2*>(out + (size_t)(row0 + 8) * O_DIM + col) = make_float2(f2, f3);
            float s0 = f0 + f2, q0 = fmaf(f0, f0, f2 * f2);
            float s1 = f1 + f3, q1 = fmaf(f1, f1, f3 * f3);
#pragma unroll
            for (int d = 4; d < 32; d <<= 1) {   // reduce across gq (rows)
                s0 += __shfl_xor_sync(0xFFFFFFFFu, s0, d);
                q0 += __shfl_xor_sync(0xFFFFFFFFu, q0, d);
                s1 += __shfl_xor_sync(0xFFFFFFFFu, s1, d);
                q1 += __shfl_xor_sync(0xFFFFFFFFu, q1, d);
            }
            if (gq == 0) {
                atomicAdd(&g_sum[col], s0);     atomicAdd(&g_ss[col], q0);
                atomicAdd(&g_sum[col + 1], s1); atomicAdd(&g_ss[col + 1], q1);
            }
        }
    } else {
#pragma unroll
        for (int cp = 0; cp < 6; cp++) {
            float s0 = 0.f, q0 = 0.f, s1 = 0.f, q1 = 0.f;
#pragma unroll
            for (int r = 0; r < 4; r++) {
                const int row = m0 + wm + gm * 4 + r;
                float* orow = out + (size_t)row * O_DIM + n0 + 32;
                uint32_t a = acc[r * 6 + cp];
                float flo = (float)(K_DIM - 2 * (int)(a & 0xFFFFu));
                float fhi = (float)(K_DIM - 2 * (int)(a >> 16));
                orow[(2 * cp) * 8 + gn]     = flo;
                orow[(2 * cp + 1) * 8 + gn] = fhi;
                s0 += flo; q0 = fmaf(flo, flo, q0);
                s1 += fhi; q1 = fmaf(fhi, fhi, q1);
            }
            // reduce across gm (lanes 8,16 apart share the same column)
            s0 += __shfl_xor_sync(0xFFFFFFFFu, s0, 8);
            s0 += __shfl_xor_sync(0xFFFFFFFFu, s0, 16);
            q0 += __shfl_xor_sync(0xFFFFFFFFu, q0, 8);
            q0 += __shfl_xor_sync(0xFFFFFFFFu, q0, 16);
            s1 += __shfl_xor_sync(0xFFFFFFFFu, s1, 8);
            s1 += __shfl_xor_sync(0xFFFFFFFFu, s1, 16);
            q1 += __shfl_xor_sync(0xFFFFFFFFu, q1, 8);
            q1 += __shfl_xor_sync(0xFFFFFFFFu, q1, 16);
            if (gm == 0) {
                int c0 = n0 + 32 + (2 * cp) * 8 + gn;
                int c1 = n0 + 32 + (2 * cp + 1) * 8 + gn;
                atomicAdd(&g_sum[c0], s0); atomicAdd(&g_ss[c0], q0);
                atomicAdd(&g_sum[c1], s1); atomicAdd(&g_ss[c1], q1);
            }
        }
    }
}

// ------------------------------ BatchNorm -----------------------------------
__global__ void bn_zero() {
    int i = blockIdx.x * blockDim.x + threadIdx.x;
    if (i < O_DIM) { g_sum[i] = 0.f; g_ss[i] = 0.f; }
}
__global__ void bn_params() {
    int c = blockIdx.x * blockDim.x + threadIdx.x;
    if (c < O_DIM) {
        float mean = g_sum[c] * (1.0f / B_DIM);
        float var = g_ss[c] * (1.0f / B_DIM) - mean * mean;
        float sc = rsqrtf(var + 1e-5f);
        g_scale[c] = sc;
        g_shift[c] = -mean * sc;
    }
}
__global__ void bn_apply(float* __restrict__ d) {
    int i = blockIdx.x * blockDim.x + threadIdx.x;
    float4 v = reinterpret_cast<float4*>(d)[i];
    int c = (i & (O_DIM / 4 - 1)) << 2;
    float4 sc = *reinterpret_cast<const float4*>(g_scale + c);
    float4 sh = *reinterpret_cast<const float4*>(g_shift + c);
    v.x = fmaf(v.x, sc.x, sh.x);
    v.y = fmaf(v.y, sc.y, sh.y);
    v.z = fmaf(v.z, sc.z, sh.z);
    v.w = fmaf(v.w, sc.w, sh.w);
    reinterpret_cast<float4*>(d)[i] = v;
}

// -------------------------------- launch -------------------------------------
extern "C" void kernel_launch(void* const* d_in, const int* in_sizes, int n_in,
                              void* d_out, int out_size) {
    const float* x = (const float*)d_in[0];
    const float* w = (const float*)d_in[1];
    float* out = (float*)d_out;

    cudaFuncSetAttribute(gemm_kernel, cudaFuncAttributeMaxDynamicSharedMemorySize, SMEM_BYTES);

    const int nx16 = B_DIM * K_DIM / 16;
    const int nt16 = nx16 + O_DIM * K_DIM / 16;
    binarize_all<<<(nt16 + 255) / 256, 256>>>(x, w, nx16, nt16);
    bn_zero<<<16, 256>>>();

    gemm_kernel<<<dim3(O_DIM / 128, B_DIM / 128), NTHREADS, SMEM_BYTES>>>(out);

    bn_params<<<16, 256>>>();
    bn_apply<<<(B_DIM * O_DIM / 4) / 256, 256>>>(out);
}